// round 6
// baseline (speedup 1.0000x reference)
#include <cuda_runtime.h>
#include <cuda_fp16.h>
#include <math.h>
#include <stdint.h>

// ---------------------------------------------------------------------------
// Problem constants
// ---------------------------------------------------------------------------
#define M_TOK   11520
#define DIM     512
#define HID     1960
#define BPRIME  16
#define NCH     40
#define OH      20
#define OW      36
#define LVEC    720
#define HP      66
#define WP      114

#define N1PAD   2048
#define K2PAD   1984

// Scratch
__device__ __half g_h  [(size_t)M_TOK * HID];     // GEMM1 output (fp16)
__device__ __half g_A1 [(size_t)M_TOK * DIM];
__device__ __half g_B1 [(size_t)N1PAD * DIM];
__device__ __half g_A2 [(size_t)M_TOK * K2PAD];
__device__ __half g_B2 [(size_t)DIM   * K2PAD];

__device__ __forceinline__ float gelu_exact(float v) {
    return 0.5f * v * (1.0f + erff(v * 0.70710678118654752f));
}

// ---------------------------------------------------------------------------
// operand prep kernels
// ---------------------------------------------------------------------------
__global__ void prep_x_kernel(const float* __restrict__ x, __half* __restrict__ A1)
{
    int idx = blockIdx.x * blockDim.x + threadIdx.x;
    if (idx >= M_TOK * DIM) return;
    A1[idx] = __float2half(x[idx]);
}

__global__ void prep_W1_kernel(const float* __restrict__ W1, __half* __restrict__ B1)
{
    int idx = blockIdx.x * blockDim.x + threadIdx.x;
    if (idx >= N1PAD * DIM) return;
    int n = idx / DIM, k = idx - n * DIM;
    float v = (n < HID) ? W1[(size_t)n * DIM + k] : 0.0f;
    B1[idx] = __float2half(v);
}

__global__ void prep_W2_kernel(const float* __restrict__ W2, __half* __restrict__ B2)
{
    int idx = blockIdx.x * blockDim.x + threadIdx.x;
    if (idx >= DIM * K2PAD) return;
    int n = idx / K2PAD, j = idx - n * K2PAD;
    float v = (j < HID) ? W2[(size_t)n * HID + j] : 0.0f;
    B2[idx] = __float2half(v);
}

// ---------------------------------------------------------------------------
// fused fold + normalize + mask + unfold + GELU  -> A2 (fp16)
// one block per (b, c) pair; pixel plane in smem.
// phase 1: scatter h (coalesced reads) into smem with atomicAdd
// phase 2: unfold + normalize + gelu -> A2
// ---------------------------------------------------------------------------
__global__ __launch_bounds__(256)
void fold_unfold_kernel(const __half* __restrict__ h, __half* __restrict__ A2)
{
    __shared__ float spix[HP * WP];          // 7524 floats = 30096 B
    const int c = blockIdx.x % NCH;
    const int b = blockIdx.x / NCH;
    const int tid = threadIdx.x;

    for (int i = tid; i < HP * WP; i += 256) spix[i] = 0.0f;
    __syncthreads();

    const __half* hb = h + ((size_t)b * LVEC) * HID + c * 49;
    for (int idx = tid; idx < LVEC * 49; idx += 256) {
        int t = idx / 49, j = idx - t * 49;
        float v = __half2float(hb[(size_t)t * HID + j]);
        int oy = t / OW, ox = t - oy * OW;
        int kh = j / 7,  kw = j - kh * 7;
        int iy = kh + 3 * oy, ix = kw + 3 * ox;
        atomicAdd(&spix[iy * WP + ix], v);
    }
    __syncthreads();

    __half* a2b = A2 + ((size_t)b * LVEC) * K2PAD + c * 49;
    for (int idx = tid; idx < LVEC * 49; idx += 256) {
        int t = idx / 49, j = idx - t * 49;
        int oy = t / OW, ox = t - oy * OW;
        int kh = j / 7,  kw = j - kh * 7;
        int iy = kh + 3 * oy, ix = kw + 3 * ox;
        float g = 0.0f;
        if (iy >= 3 && iy < 63 && ix >= 3 && ix < 111) {
            int oy_lo = max(0, (iy - 4) / 3);
            int oy_hi = min(OH - 1, iy / 3);
            int ox_lo = max(0, (ix - 4) / 3);
            int ox_hi = min(OW - 1, ix / 3);
            float cnt = (float)((oy_hi - oy_lo + 1) * (ox_hi - ox_lo + 1));
            g = gelu_exact(spix[iy * WP + ix] / cnt);
        }
        a2b[(size_t)t * K2PAD + j] = __float2half(g);
    }

    // zero-pad columns [1960, 1984)
    if (c == NCH - 1) {
        for (int idx = tid; idx < LVEC * (K2PAD - HID); idx += 256) {
            int t = idx / (K2PAD - HID), j = idx - t * (K2PAD - HID);
            A2[((size_t)(b * LVEC + t)) * K2PAD + HID + j] = __float2half(0.0f);
        }
    }
}

// ---------------------------------------------------------------------------
// fp16 mma.sync GEMM. C[m,n] = sum_k A[m,k]*B[n,k] + bias[n]
// BM=128, 8 warps (4m x 2n), warp tile 32 x WN, BK=64 halves (SW128 rows),
// 3-stage cp.async. LDSM addresses hoisted; k16 swizzle via XOR.
// ---------------------------------------------------------------------------
#define STAGES 3

__device__ __forceinline__ uint32_t smem_u32(const void* p) {
    return (uint32_t)__cvta_generic_to_shared(p);
}

template<int BN, int WN, int MINCTA, typename OutT>
__global__ __launch_bounds__(256, MINCTA)
void gemm_fp16_mma(const __half* __restrict__ A, const __half* __restrict__ B,
                   const float* __restrict__ bias, OutT* __restrict__ C,
                   int KT, int kbytes, int Nstore, int ldc)
{
    constexpr int STAGE_BYTES = (128 + BN) * 128;
    constexpr int NB16 = WN / 16;
    constexpr int NJ   = WN / 8;

    extern __shared__ char smem[];
    uint32_t sbase = smem_u32(smem);
    const int tid  = threadIdx.x;
    const int wid  = tid >> 5;
    const int lane = tid & 31;
    const int wm   = wid >> 1;
    const int wn   = wid & 1;
    const int m0   = blockIdx.y * 128;
    const int n0   = blockIdx.x * BN;

    const char* Ab = (const char*)A + (size_t)m0 * kbytes;
    const char* Bb = (const char*)B + (size_t)n0 * kbytes;

    float acc[2][NJ][4];
#pragma unroll
    for (int i = 0; i < 2; i++)
#pragma unroll
        for (int j = 0; j < NJ; j++)
#pragma unroll
            for (int q = 0; q < 4; q++) acc[i][j][q] = 0.0f;

    auto load_stage = [&](int s, int kt2) {
        uint32_t st = sbase + s * STAGE_BYTES;
        size_t koff = (size_t)kt2 * 128;
#pragma unroll
        for (int i = 0; i < 4; i++) {               // A: 128 rows
            int id  = tid + i * 256;
            int row = id >> 3;
            int c   = id & 7;
            uint32_t so = (uint32_t)(row * 128 + ((c ^ (row & 7)) << 4));
            const char* ga = Ab + (size_t)row * kbytes + koff + ((size_t)c << 4);
            asm volatile("cp.async.cg.shared.global [%0], [%1], 16;" :: "r"(st + so), "l"(ga) : "memory");
        }
#pragma unroll
        for (int i = 0; i < BN / 32; i++) {         // B: BN rows
            int id  = tid + i * 256;
            int row = id >> 3;
            int c   = id & 7;
            uint32_t so = (uint32_t)(row * 128 + ((c ^ (row & 7)) << 4));
            const char* gb = Bb + (size_t)row * kbytes + koff + ((size_t)c << 4);
            asm volatile("cp.async.cg.shared.global [%0], [%1], 16;" :: "r"(st + 16384 + so), "l"(gb) : "memory");
        }
        asm volatile("cp.async.commit_group;" ::: "memory");
    };

    // hoisted fragment smem offsets (within stage); k16 applied as XOR(k16<<5)
    const int lrow = lane & 15;
    const int lch  = lane >> 4;
    uint32_t offA[2], offB[NB16];
#pragma unroll
    for (int i = 0; i < 2; i++) {
        int r = wm * 32 + i * 16 + lrow;
        offA[i] = (uint32_t)(r * 128 + ((lch ^ (r & 7)) << 4));
    }
#pragma unroll
    for (int j = 0; j < NB16; j++) {
        int r = wn * WN + j * 16 + lrow;
        offB[j] = (uint32_t)(16384 + r * 128 + ((lch ^ (r & 7)) << 4));
    }

    // prologue
#pragma unroll
    for (int p = 0; p < STAGES - 1; p++) load_stage(p, p);

    for (int kt = 0; kt < KT; kt++) {
        int s = kt % STAGES;
        asm volatile("cp.async.wait_group 1;" ::: "memory");
        __syncthreads();

        int ktn = kt + STAGES - 1;
        if (ktn < KT) load_stage(ktn % STAGES, ktn);
        else          asm volatile("cp.async.commit_group;" ::: "memory");

        uint32_t sA = sbase + s * STAGE_BYTES;

#pragma unroll
        for (int k16 = 0; k16 < 4; k16++) {
            const uint32_t kx = (uint32_t)(k16 << 5);
            uint32_t a[2][4], b[NB16][4];
#pragma unroll
            for (int i = 0; i < 2; i++) {
                asm volatile("ldmatrix.sync.aligned.m8n8.x4.shared.b16 {%0,%1,%2,%3}, [%4];"
                             : "=r"(a[i][0]), "=r"(a[i][1]), "=r"(a[i][2]), "=r"(a[i][3])
                             : "r"(sA + (offA[i] ^ kx)));
            }
#pragma unroll
            for (int j = 0; j < NB16; j++) {
                asm volatile("ldmatrix.sync.aligned.m8n8.x4.shared.b16 {%0,%1,%2,%3}, [%4];"
                             : "=r"(b[j][0]), "=r"(b[j][1]), "=r"(b[j][2]), "=r"(b[j][3])
                             : "r"(sA + (offB[j] ^ kx)));
            }
#pragma unroll
            for (int i = 0; i < 2; i++) {
#pragma unroll
                for (int jn = 0; jn < NJ; jn++) {
                    int jj = jn >> 1;
                    uint32_t b0 = (jn & 1) ? b[jj][1] : b[jj][0];
                    uint32_t b1 = (jn & 1) ? b[jj][3] : b[jj][2];
                    asm volatile(
                        "mma.sync.aligned.m16n8k16.row.col.f32.f16.f16.f32 "
                        "{%0,%1,%2,%3}, {%4,%5,%6,%7}, {%8,%9}, {%0,%1,%2,%3};"
                        : "+f"(acc[i][jn][0]), "+f"(acc[i][jn][1]),
                          "+f"(acc[i][jn][2]), "+f"(acc[i][jn][3])
                        : "r"(a[i][0]), "r"(a[i][1]), "r"(a[i][2]), "r"(a[i][3]),
                          "r"(b0), "r"(b1));
                }
            }
        }
    }

    // epilogue: bias + store
    const int g  = lane >> 2;
    const int tg = lane & 3;
#pragma unroll
    for (int i = 0; i < 2; i++) {
        int r0 = m0 + wm * 32 + i * 16 + g;
#pragma unroll
        for (int jn = 0; jn < NJ; jn++) {
            int col = n0 + wn * WN + jn * 8 + tg * 2;
            if (col < Nstore) {
                float bx = bias[col], by = bias[col + 1];
                float c00 = acc[i][jn][0] + bx, c01 = acc[i][jn][1] + by;
                float c10 = acc[i][jn][2] + bx, c11 = acc[i][jn][3] + by;
                if constexpr (sizeof(OutT) == 2) {
                    __half2 v0 = __floats2half2_rn(c00, c01);
                    __half2 v1 = __floats2half2_rn(c10, c11);
                    *reinterpret_cast<__half2*>((__half*)C + (size_t)r0       * ldc + col) = v0;
                    *reinterpret_cast<__half2*>((__half*)C + (size_t)(r0 + 8) * ldc + col) = v1;
                } else {
                    *reinterpret_cast<float2*>((float*)C + (size_t)r0       * ldc + col) = make_float2(c00, c01);
                    *reinterpret_cast<float2*>((float*)C + (size_t)(r0 + 8) * ldc + col) = make_float2(c10, c11);
                }
            }
        }
    }
}

// ---------------------------------------------------------------------------
// launch
// ---------------------------------------------------------------------------
extern "C" void kernel_launch(void* const* d_in, const int* in_sizes, int n_in,
                              void* d_out, int out_size)
{
    const float* x  = (const float*)d_in[0];
    const float* W1 = (const float*)d_in[1];
    const float* b1 = (const float*)d_in[2];
    const float* W2 = (const float*)d_in[3];
    const float* b2 = (const float*)d_in[4];
    float* out = (float*)d_out;

    __half *h_ptr, *A1, *B1, *A2, *B2;
    cudaGetSymbolAddress((void**)&h_ptr, g_h);
    cudaGetSymbolAddress((void**)&A1, g_A1);
    cudaGetSymbolAddress((void**)&B1, g_B1);
    cudaGetSymbolAddress((void**)&A2, g_A2);
    cudaGetSymbolAddress((void**)&B2, g_B2);

    constexpr int SMEM1 = STAGES * (128 + 128) * 128;   // 98304
    constexpr int SMEM2 = STAGES * (128 + 64) * 128;    // 73728
    cudaFuncSetAttribute((const void*)gemm_fp16_mma<128, 64, 2, __half>,
                         cudaFuncAttributeMaxDynamicSharedMemorySize, SMEM1);
    cudaFuncSetAttribute((const void*)gemm_fp16_mma<64, 32, 3, float>,
                         cudaFuncAttributeMaxDynamicSharedMemorySize, SMEM2);

    { int n = M_TOK * DIM;   prep_x_kernel <<<(n + 255) / 256, 256>>>(x,  A1); }
    { int n = N1PAD * DIM;   prep_W1_kernel<<<(n + 255) / 256, 256>>>(W1, B1); }
    { int n = DIM * K2PAD;   prep_W2_kernel<<<(n + 255) / 256, 256>>>(W2, B2); }

    // GEMM1: g_h(fp16) = x @ W1^T + b1   (M=11520, N=1960(pad2048), K=512)
    {
        dim3 grid(N1PAD / 128, M_TOK / 128);
        gemm_fp16_mma<128, 64, 2, __half><<<grid, 256, SMEM1>>>(A1, B1, b1, h_ptr,
                                                                DIM / 64, DIM * 2, HID, HID);
    }
    // fused fold + normalize + unfold + GELU -> A2
    {
        fold_unfold_kernel<<<BPRIME * NCH, 256>>>(h_ptr, A2);
    }
    // GEMM2: out = gelu(y) @ W2^T + b2   (M=11520, N=512, K=1960(pad1984))
    {
        dim3 grid(DIM / 64, M_TOK / 128);
        gemm_fp16_mma<64, 32, 3, float><<<grid, 256, SMEM2>>>(A2, B2, b2, out,
                                                              K2PAD / 64, K2PAD * 2, DIM, DIM);
    }
}

// round 7
// speedup vs baseline: 1.0227x; 1.0227x over previous
#include <cuda_runtime.h>
#include <cuda_fp16.h>
#include <math.h>
#include <stdint.h>

// ---------------------------------------------------------------------------
// Problem constants
// ---------------------------------------------------------------------------
#define M_TOK   11520
#define DIM     512
#define HID     1960
#define BPRIME  16
#define NCH     40
#define OH      20
#define OW      36
#define LVEC    720
#define HP      66
#define WP      114
#define NPIX    (BPRIME*NCH*HP*WP)

#define N1PAD   2048
#define K2PAD   1984

// Scratch
__device__ __half g_h  [(size_t)M_TOK * HID];     // GEMM1 output (fp16)
__device__ float  g_pix[(size_t)NPIX];
__device__ __half g_A1 [(size_t)M_TOK * DIM];
__device__ __half g_B1 [(size_t)N1PAD * DIM];
__device__ __half g_A2 [(size_t)M_TOK * K2PAD];
__device__ __half g_B2 [(size_t)DIM   * K2PAD];

__device__ __forceinline__ float gelu_exact(float v) {
    return 0.5f * v * (1.0f + erff(v * 0.70710678118654752f));
}

// ---------------------------------------------------------------------------
// operand prep kernels
// ---------------------------------------------------------------------------
__global__ void prep_x_kernel(const float* __restrict__ x, __half* __restrict__ A1)
{
    int idx = blockIdx.x * blockDim.x + threadIdx.x;
    if (idx >= M_TOK * DIM) return;
    A1[idx] = __float2half(x[idx]);
}

__global__ void prep_W1_kernel(const float* __restrict__ W1, __half* __restrict__ B1)
{
    int idx = blockIdx.x * blockDim.x + threadIdx.x;
    if (idx >= N1PAD * DIM) return;
    int n = idx / DIM, k = idx - n * DIM;
    float v = (n < HID) ? W1[(size_t)n * DIM + k] : 0.0f;
    B1[idx] = __float2half(v);
}

__global__ void prep_W2_kernel(const float* __restrict__ W2, __half* __restrict__ B2)
{
    int idx = blockIdx.x * blockDim.x + threadIdx.x;
    if (idx >= DIM * K2PAD) return;
    int n = idx / K2PAD, j = idx - n * K2PAD;
    float v = (j < HID) ? W2[(size_t)n * HID + j] : 0.0f;
    B2[idx] = __float2half(v);
}

// ---------------------------------------------------------------------------
// fold + normalize + border-mask (gather, no atomics), h in fp16
// ---------------------------------------------------------------------------
__global__ void fold_div_kernel(const __half* __restrict__ h, float* __restrict__ pix)
{
    int idx = blockIdx.x * blockDim.x + threadIdx.x;
    if (idx >= NPIX) return;
    int ix = idx % WP;
    int t  = idx / WP;
    int iy = t % HP;  t /= HP;
    int c  = t % NCH;
    int b  = t / NCH;

    float val = 0.0f;
    if (iy >= 3 && iy < 63 && ix >= 3 && ix < 111) {
        int oy_lo = max(0, (iy - 4) / 3);
        int oy_hi = min(OH - 1, iy / 3);
        int ox_lo = max(0, (ix - 4) / 3);
        int ox_hi = min(OW - 1, ix / 3);
        int cnt = (oy_hi - oy_lo + 1) * (ox_hi - ox_lo + 1);
        float acc = 0.0f;
        for (int oy = oy_lo; oy <= oy_hi; oy++) {
            int kh = iy - 3 * oy;
            for (int ox = ox_lo; ox <= ox_hi; ox++) {
                int kw = ix - 3 * ox;
                int token = b * LVEC + oy * OW + ox;
                acc += __half2float(h[(size_t)token * HID + c * 49 + kh * 7 + kw]);
            }
        }
        val = acc / (float)cnt;
    }
    pix[idx] = val;
}

// unfold + GELU -> fp16 A2
__global__ void prep_A2_kernel(const float* __restrict__ pix, __half* __restrict__ A2)
{
    long long idx = (long long)blockIdx.x * blockDim.x + threadIdx.x;
    if (idx >= (long long)M_TOK * K2PAD) return;
    int token = (int)(idx / K2PAD);
    int j     = (int)(idx - (long long)token * K2PAD);
    float g = 0.0f;
    if (j < HID) {
        int b  = token / LVEC;
        int l  = token - b * LVEC;
        int oy = l / OW, ox = l - oy * OW;
        int c  = j / 49;
        int r  = j - c * 49;
        int kh = r / 7, kw = r - kh * 7;
        int iy = kh + 3 * oy;
        int ix = kw + 3 * ox;
        float y = pix[(((size_t)b * NCH + c) * HP + iy) * WP + ix];
        g = gelu_exact(y);
    }
    A2[idx] = __float2half(g);
}

// ---------------------------------------------------------------------------
// fp16 mma.sync GEMM. C[m,n] = sum_k A[m,k]*B[n,k] + bias[n]
// CTA tile 256x128, 8 warps (4m x 2n), warp tile 64x64.
// BK=64 halves (128B SW128 rows), 3-stage cp.async, occ 1.
// ---------------------------------------------------------------------------
#define STAGES 3
#define BM 256
#define BN 128
#define STAGE_BYTES ((BM + BN) * 128)          // 49152
#define GEMM_SMEM   (STAGES * STAGE_BYTES)     // 147456
#define A_BYTES     (BM * 128)                 // 32768

__device__ __forceinline__ uint32_t smem_u32(const void* p) {
    return (uint32_t)__cvta_generic_to_shared(p);
}

template<typename OutT>
__global__ __launch_bounds__(256, 1)
void gemm_fp16_mma(const __half* __restrict__ A, const __half* __restrict__ B,
                   const float* __restrict__ bias, OutT* __restrict__ C,
                   int KT, int kbytes, int Nstore, int ldc)
{
    extern __shared__ char smem[];
    uint32_t sbase = smem_u32(smem);
    const int tid  = threadIdx.x;
    const int wid  = tid >> 5;
    const int lane = tid & 31;
    const int wm   = wid >> 1;          // 0..3 -> m offset 64*wm
    const int wn   = wid & 1;           // 0..1 -> n offset 64*wn
    const int m0   = blockIdx.y * BM;
    const int n0   = blockIdx.x * BN;

    const char* Ab = (const char*)A + (size_t)m0 * kbytes;
    const char* Bb = (const char*)B + (size_t)n0 * kbytes;

    float acc[4][8][4];
#pragma unroll
    for (int i = 0; i < 4; i++)
#pragma unroll
        for (int j = 0; j < 8; j++)
#pragma unroll
            for (int q = 0; q < 4; q++) acc[i][j][q] = 0.0f;

    auto load_stage = [&](int s, int kt2) {
        uint32_t st = sbase + s * STAGE_BYTES;
        size_t koff = (size_t)kt2 * 128;
#pragma unroll
        for (int i = 0; i < 8; i++) {               // A: 256 rows * 8 chunks
            int id  = tid + i * 256;
            int row = id >> 3;
            int c   = id & 7;
            uint32_t so = (uint32_t)(row * 128 + ((c ^ (row & 7)) << 4));
            const char* ga = Ab + (size_t)row * kbytes + koff + ((size_t)c << 4);
            asm volatile("cp.async.cg.shared.global [%0], [%1], 16;" :: "r"(st + so), "l"(ga) : "memory");
        }
#pragma unroll
        for (int i = 0; i < 4; i++) {               // B: 128 rows * 8 chunks
            int id  = tid + i * 256;
            int row = id >> 3;
            int c   = id & 7;
            uint32_t so = (uint32_t)(row * 128 + ((c ^ (row & 7)) << 4));
            const char* gb = Bb + (size_t)row * kbytes + koff + ((size_t)c << 4);
            asm volatile("cp.async.cg.shared.global [%0], [%1], 16;" :: "r"(st + A_BYTES + so), "l"(gb) : "memory");
        }
        asm volatile("cp.async.commit_group;" ::: "memory");
    };

    // hoisted fragment offsets; k16 applied as XOR(k16<<5)
    const int lrow = lane & 15;
    const int lch  = lane >> 4;
    uint32_t offA[4], offB[4];
#pragma unroll
    for (int i = 0; i < 4; i++) {
        int r = wm * 64 + i * 16 + lrow;
        offA[i] = (uint32_t)(r * 128 + ((lch ^ (r & 7)) << 4));
    }
#pragma unroll
    for (int j = 0; j < 4; j++) {
        int r = wn * 64 + j * 16 + lrow;
        offB[j] = (uint32_t)(A_BYTES + r * 128 + ((lch ^ (r & 7)) << 4));
    }

    // prologue
#pragma unroll
    for (int p = 0; p < STAGES - 1; p++) load_stage(p, p);

    for (int kt = 0; kt < KT; kt++) {
        int s = kt % STAGES;
        asm volatile("cp.async.wait_group 1;" ::: "memory");
        __syncthreads();

        int ktn = kt + STAGES - 1;
        if (ktn < KT) load_stage(ktn % STAGES, ktn);
        else          asm volatile("cp.async.commit_group;" ::: "memory");

        uint32_t sA = sbase + s * STAGE_BYTES;

#pragma unroll
        for (int k16 = 0; k16 < 4; k16++) {
            const uint32_t kx = (uint32_t)(k16 << 5);
            uint32_t a[4][4], b[4][4];
#pragma unroll
            for (int i = 0; i < 4; i++) {
                asm volatile("ldmatrix.sync.aligned.m8n8.x4.shared.b16 {%0,%1,%2,%3}, [%4];"
                             : "=r"(a[i][0]), "=r"(a[i][1]), "=r"(a[i][2]), "=r"(a[i][3])
                             : "r"(sA + (offA[i] ^ kx)));
            }
#pragma unroll
            for (int j = 0; j < 4; j++) {
                asm volatile("ldmatrix.sync.aligned.m8n8.x4.shared.b16 {%0,%1,%2,%3}, [%4];"
                             : "=r"(b[j][0]), "=r"(b[j][1]), "=r"(b[j][2]), "=r"(b[j][3])
                             : "r"(sA + (offB[j] ^ kx)));
            }
#pragma unroll
            for (int i = 0; i < 4; i++) {
#pragma unroll
                for (int jn = 0; jn < 8; jn++) {
                    int jj = jn >> 1;
                    uint32_t b0 = (jn & 1) ? b[jj][1] : b[jj][0];
                    uint32_t b1 = (jn & 1) ? b[jj][3] : b[jj][2];
                    asm volatile(
                        "mma.sync.aligned.m16n8k16.row.col.f32.f16.f16.f32 "
                        "{%0,%1,%2,%3}, {%4,%5,%6,%7}, {%8,%9}, {%0,%1,%2,%3};"
                        : "+f"(acc[i][jn][0]), "+f"(acc[i][jn][1]),
                          "+f"(acc[i][jn][2]), "+f"(acc[i][jn][3])
                        : "r"(a[i][0]), "r"(a[i][1]), "r"(a[i][2]), "r"(a[i][3]),
                          "r"(b0), "r"(b1));
                }
            }
        }
    }

    // epilogue: bias + store
    const int g  = lane >> 2;
    const int tg = lane & 3;
#pragma unroll
    for (int i = 0; i < 4; i++) {
        int r0 = m0 + wm * 64 + i * 16 + g;
#pragma unroll
        for (int jn = 0; jn < 8; jn++) {
            int col = n0 + wn * 64 + jn * 8 + tg * 2;
            if (col < Nstore) {
                float bx = bias[col], by = bias[col + 1];
                float c00 = acc[i][jn][0] + bx, c01 = acc[i][jn][1] + by;
                float c10 = acc[i][jn][2] + bx, c11 = acc[i][jn][3] + by;
                if constexpr (sizeof(OutT) == 2) {
                    *reinterpret_cast<__half2*>((__half*)C + (size_t)r0       * ldc + col) = __floats2half2_rn(c00, c01);
                    *reinterpret_cast<__half2*>((__half*)C + (size_t)(r0 + 8) * ldc + col) = __floats2half2_rn(c10, c11);
                } else {
                    *reinterpret_cast<float2*>((float*)C + (size_t)r0       * ldc + col) = make_float2(c00, c01);
                    *reinterpret_cast<float2*>((float*)C + (size_t)(r0 + 8) * ldc + col) = make_float2(c10, c11);
                }
            }
        }
    }
}

// ---------------------------------------------------------------------------
// launch
// ---------------------------------------------------------------------------
extern "C" void kernel_launch(void* const* d_in, const int* in_sizes, int n_in,
                              void* d_out, int out_size)
{
    const float* x  = (const float*)d_in[0];
    const float* W1 = (const float*)d_in[1];
    const float* b1 = (const float*)d_in[2];
    const float* W2 = (const float*)d_in[3];
    const float* b2 = (const float*)d_in[4];
    float* out = (float*)d_out;

    __half *h_ptr, *A1, *B1, *A2, *B2;
    float *pix_ptr;
    cudaGetSymbolAddress((void**)&h_ptr,   g_h);
    cudaGetSymbolAddress((void**)&pix_ptr, g_pix);
    cudaGetSymbolAddress((void**)&A1, g_A1);
    cudaGetSymbolAddress((void**)&B1, g_B1);
    cudaGetSymbolAddress((void**)&A2, g_A2);
    cudaGetSymbolAddress((void**)&B2, g_B2);

    cudaFuncSetAttribute((const void*)gemm_fp16_mma<__half>,
                         cudaFuncAttributeMaxDynamicSharedMemorySize, GEMM_SMEM);
    cudaFuncSetAttribute((const void*)gemm_fp16_mma<float>,
                         cudaFuncAttributeMaxDynamicSharedMemorySize, GEMM_SMEM);

    { int n = M_TOK * DIM;   prep_x_kernel <<<(n + 255) / 256, 256>>>(x,  A1); }
    { int n = N1PAD * DIM;   prep_W1_kernel<<<(n + 255) / 256, 256>>>(W1, B1); }
    { int n = DIM * K2PAD;   prep_W2_kernel<<<(n + 255) / 256, 256>>>(W2, B2); }

    // GEMM1: g_h(fp16) = x @ W1^T + b1   (M=11520, N=1960(pad2048), K=512)
    {
        dim3 grid(N1PAD / BN, M_TOK / BM);   // (16, 45)
        gemm_fp16_mma<__half><<<grid, 256, GEMM_SMEM>>>(A1, B1, b1, h_ptr,
                                                        DIM / 64, DIM * 2, HID, HID);
    }
    // fold + normalize + mask
    {
        int blocks = (NPIX + 255) / 256;
        fold_div_kernel<<<blocks, 256>>>(h_ptr, pix_ptr);
    }
    // unfold + GELU -> A2
    {
        long long n = (long long)M_TOK * K2PAD;
        prep_A2_kernel<<<(int)((n + 255) / 256), 256>>>(pix_ptr, A2);
    }
    // GEMM2: out = gelu(y) @ W2^T + b2   (M=11520, N=512, K=1960(pad1984))
    {
        dim3 grid(DIM / BN, M_TOK / BM);     // (4, 45)
        gemm_fp16_mma<float><<<grid, 256, GEMM_SMEM>>>(A2, B2, b2, out,
                                                       K2PAD / 64, K2PAD * 2, DIM, DIM);
    }
}

// round 9
// speedup vs baseline: 1.1698x; 1.1438x over previous
#include <cuda_runtime.h>
#include <cuda_fp16.h>
#include <math.h>
#include <stdint.h>

// ---------------------------------------------------------------------------
// Problem constants
// ---------------------------------------------------------------------------
#define M_TOK   11520
#define DIM     512
#define HID     1960
#define BPRIME  16
#define NCH     40
#define OH      20
#define OW      36
#define LVEC    720
#define HP      66
#define WP      114
#define NPIX    (BPRIME*NCH*HP*WP)

#define N1PAD   2048
#define K2PAD   1984

// Scratch
__device__ __half g_h  [(size_t)M_TOK * HID];
__device__ float  g_pix[(size_t)NPIX];
__device__ __half g_A1 [(size_t)M_TOK * DIM];
__device__ __half g_B1 [(size_t)N1PAD * DIM];
__device__ __half g_A2 [(size_t)M_TOK * K2PAD];
__device__ __half g_B2 [(size_t)DIM   * K2PAD];

__device__ __forceinline__ float gelu_exact(float v) {
    return 0.5f * v * (1.0f + erff(v * 0.70710678118654752f));
}

// ---------------------------------------------------------------------------
// operand prep kernels
// ---------------------------------------------------------------------------
__global__ void prep_x_kernel(const float* __restrict__ x, __half* __restrict__ A1)
{
    int idx = blockIdx.x * blockDim.x + threadIdx.x;
    if (idx >= M_TOK * DIM) return;
    A1[idx] = __float2half(x[idx]);
}

__global__ void prep_W1_kernel(const float* __restrict__ W1, __half* __restrict__ B1)
{
    int idx = blockIdx.x * blockDim.x + threadIdx.x;
    if (idx >= N1PAD * DIM) return;
    int n = idx / DIM, k = idx - n * DIM;
    float v = (n < HID) ? W1[(size_t)n * DIM + k] : 0.0f;
    B1[idx] = __float2half(v);
}

__global__ void prep_W2_kernel(const float* __restrict__ W2, __half* __restrict__ B2)
{
    int idx = blockIdx.x * blockDim.x + threadIdx.x;
    if (idx >= DIM * K2PAD) return;
    int n = idx / K2PAD, j = idx - n * K2PAD;
    float v = (j < HID) ? W2[(size_t)n * HID + j] : 0.0f;
    B2[idx] = __float2half(v);
}

// ---------------------------------------------------------------------------
// fold + normalize + border-mask (gather, no atomics), h in fp16
// ---------------------------------------------------------------------------
__global__ void fold_div_kernel(const __half* __restrict__ h, float* __restrict__ pix)
{
    int idx = blockIdx.x * blockDim.x + threadIdx.x;
    if (idx >= NPIX) return;
    int ix = idx % WP;
    int t  = idx / WP;
    int iy = t % HP;  t /= HP;
    int c  = t % NCH;
    int b  = t / NCH;

    float val = 0.0f;
    if (iy >= 3 && iy < 63 && ix >= 3 && ix < 111) {
        int oy_lo = max(0, (iy - 4) / 3);
        int oy_hi = min(OH - 1, iy / 3);
        int ox_lo = max(0, (ix - 4) / 3);
        int ox_hi = min(OW - 1, ix / 3);
        int cnt = (oy_hi - oy_lo + 1) * (ox_hi - ox_lo + 1);
        float acc = 0.0f;
        for (int oy = oy_lo; oy <= oy_hi; oy++) {
            int kh = iy - 3 * oy;
            for (int ox = ox_lo; ox <= ox_hi; ox++) {
                int kw = ix - 3 * ox;
                int token = b * LVEC + oy * OW + ox;
                acc += __half2float(h[(size_t)token * HID + c * 49 + kh * 7 + kw]);
            }
        }
        val = acc / (float)cnt;
    }
    pix[idx] = val;
}

// unfold + GELU -> fp16 A2
__global__ void prep_A2_kernel(const float* __restrict__ pix, __half* __restrict__ A2)
{
    long long idx = (long long)blockIdx.x * blockDim.x + threadIdx.x;
    if (idx >= (long long)M_TOK * K2PAD) return;
    int token = (int)(idx / K2PAD);
    int j     = (int)(idx - (long long)token * K2PAD);
    float g = 0.0f;
    if (j < HID) {
        int b  = token / LVEC;
        int l  = token - b * LVEC;
        int oy = l / OW, ox = l - oy * OW;
        int c  = j / 49;
        int r  = j - c * 49;
        int kh = r / 7, kw = r - kh * 7;
        int iy = kh + 3 * oy;
        int ix = kw + 3 * ox;
        float y = pix[(((size_t)b * NCH + c) * HP + iy) * WP + ix];
        g = gelu_exact(y);
    }
    A2[idx] = __float2half(g);
}

// ---------------------------------------------------------------------------
// fp16 mma.sync GEMM. C[m,n] = sum_k A[m,k]*B[n,k] + bias[n]
// 256 threads = 8 warps, (BMt/WM) x (BNt/WN) warp grid (product must be 8).
// BK=64 halves (128B SW128 rows), 3-stage cp.async.
// ---------------------------------------------------------------------------
#define STAGES 3

__device__ __forceinline__ uint32_t smem_u32(const void* p) {
    return (uint32_t)__cvta_generic_to_shared(p);
}

template<int BMt, int BNt, int WM, int WN, int MINCTA, typename OutT>
__global__ __launch_bounds__(256, MINCTA)
void gemm_fp16_mma(const __half* __restrict__ A, const __half* __restrict__ B,
                   const float* __restrict__ bias, OutT* __restrict__ C,
                   int KT, int kbytes, int Nstore, int ldc)
{
    constexpr int STAGE_BYTES = (BMt + BNt) * 128;
    constexpr int A_BYTES     = BMt * 128;
    constexpr int NWN  = BNt / WN;       // warps along n
    constexpr int NI   = WM / 16;        // a-frags per warp
    constexpr int NB16 = WN / 16;        // b x4-ldmatrix per k16
    constexpr int NJ   = WN / 8;         // mma n-steps
    static_assert((BMt / WM) * NWN == 8, "warp grid must have 8 warps");

    extern __shared__ char smem[];
    uint32_t sbase = smem_u32(smem);
    const int tid  = threadIdx.x;
    const int wid  = tid >> 5;
    const int lane = tid & 31;
    const int wm   = wid / NWN;
    const int wn   = wid % NWN;
    const int m0   = blockIdx.y * BMt;
    const int n0   = blockIdx.x * BNt;

    const char* Ab = (const char*)A + (size_t)m0 * kbytes;
    const char* Bb = (const char*)B + (size_t)n0 * kbytes;

    float acc[NI][NJ][4];
#pragma unroll
    for (int i = 0; i < NI; i++)
#pragma unroll
        for (int j = 0; j < NJ; j++)
#pragma unroll
            for (int q = 0; q < 4; q++) acc[i][j][q] = 0.0f;

    auto load_stage = [&](int s, int kt2) {
        uint32_t st = sbase + s * STAGE_BYTES;
        size_t koff = (size_t)kt2 * 128;
#pragma unroll
        for (int i = 0; i < BMt / 32; i++) {
            int id  = tid + i * 256;
            int row = id >> 3;
            int c   = id & 7;
            uint32_t so = (uint32_t)(row * 128 + ((c ^ (row & 7)) << 4));
            const char* ga = Ab + (size_t)row * kbytes + koff + ((size_t)c << 4);
            asm volatile("cp.async.cg.shared.global [%0], [%1], 16;" :: "r"(st + so), "l"(ga) : "memory");
        }
#pragma unroll
        for (int i = 0; i < BNt / 32; i++) {
            int id  = tid + i * 256;
            int row = id >> 3;
            int c   = id & 7;
            uint32_t so = (uint32_t)(row * 128 + ((c ^ (row & 7)) << 4));
            const char* gb = Bb + (size_t)row * kbytes + koff + ((size_t)c << 4);
            asm volatile("cp.async.cg.shared.global [%0], [%1], 16;" :: "r"(st + A_BYTES + so), "l"(gb) : "memory");
        }
        asm volatile("cp.async.commit_group;" ::: "memory");
    };

    // hoisted fragment offsets; k16 applied as XOR(k16<<5)
    const int lrow = lane & 15;
    const int lch  = lane >> 4;
    uint32_t offA[NI], offB[NB16];
#pragma unroll
    for (int i = 0; i < NI; i++) {
        int r = wm * WM + i * 16 + lrow;
        offA[i] = (uint32_t)(r * 128 + ((lch ^ (r & 7)) << 4));
    }
#pragma unroll
    for (int j = 0; j < NB16; j++) {
        int r = wn * WN + j * 16 + lrow;
        offB[j] = (uint32_t)(A_BYTES + r * 128 + ((lch ^ (r & 7)) << 4));
    }

    // prologue
#pragma unroll
    for (int p = 0; p < STAGES - 1; p++) load_stage(p, p);

    for (int kt = 0; kt < KT; kt++) {
        int s = kt % STAGES;
        asm volatile("cp.async.wait_group 1;" ::: "memory");
        __syncthreads();

        int ktn = kt + STAGES - 1;
        if (ktn < KT) load_stage(ktn % STAGES, ktn);
        else          asm volatile("cp.async.commit_group;" ::: "memory");

        uint32_t sA = sbase + s * STAGE_BYTES;

#pragma unroll
        for (int k16 = 0; k16 < 4; k16++) {
            const uint32_t kx = (uint32_t)(k16 << 5);
            uint32_t a[NI][4], b[NB16][4];
#pragma unroll
            for (int i = 0; i < NI; i++) {
                asm volatile("ldmatrix.sync.aligned.m8n8.x4.shared.b16 {%0,%1,%2,%3}, [%4];"
                             : "=r"(a[i][0]), "=r"(a[i][1]), "=r"(a[i][2]), "=r"(a[i][3])
                             : "r"(sA + (offA[i] ^ kx)));
            }
#pragma unroll
            for (int j = 0; j < NB16; j++) {
                asm volatile("ldmatrix.sync.aligned.m8n8.x4.shared.b16 {%0,%1,%2,%3}, [%4];"
                             : "=r"(b[j][0]), "=r"(b[j][1]), "=r"(b[j][2]), "=r"(b[j][3])
                             : "r"(sA + (offB[j] ^ kx)));
            }
#pragma unroll
            for (int i = 0; i < NI; i++) {
#pragma unroll
                for (int jn = 0; jn < NJ; jn++) {
                    int jj = jn >> 1;
                    uint32_t b0 = (jn & 1) ? b[jj][1] : b[jj][0];
                    uint32_t b1 = (jn & 1) ? b[jj][3] : b[jj][2];
                    asm volatile(
                        "mma.sync.aligned.m16n8k16.row.col.f32.f16.f16.f32 "
                        "{%0,%1,%2,%3}, {%4,%5,%6,%7}, {%8,%9}, {%0,%1,%2,%3};"
                        : "+f"(acc[i][jn][0]), "+f"(acc[i][jn][1]),
                          "+f"(acc[i][jn][2]), "+f"(acc[i][jn][3])
                        : "r"(a[i][0]), "r"(a[i][1]), "r"(a[i][2]), "r"(a[i][3]),
                          "r"(b0), "r"(b1));
                }
            }
        }
    }

    // epilogue: bias + store
    const int g  = lane >> 2;
    const int tg = lane & 3;
#pragma unroll
    for (int i = 0; i < NI; i++) {
        int r0 = m0 + wm * WM + i * 16 + g;
#pragma unroll
        for (int jn = 0; jn < NJ; jn++) {
            int col = n0 + wn * WN + jn * 8 + tg * 2;
            if (col < Nstore) {
                float bx = bias[col], by = bias[col + 1];
                float c00 = acc[i][jn][0] + bx, c01 = acc[i][jn][1] + by;
                float c10 = acc[i][jn][2] + bx, c11 = acc[i][jn][3] + by;
                if constexpr (sizeof(OutT) == 2) {
                    *reinterpret_cast<__half2*>((__half*)C + (size_t)r0       * ldc + col) = __floats2half2_rn(c00, c01);
                    *reinterpret_cast<__half2*>((__half*)C + (size_t)(r0 + 8) * ldc + col) = __floats2half2_rn(c10, c11);
                } else {
                    *reinterpret_cast<float2*>((float*)C + (size_t)r0       * ldc + col) = make_float2(c00, c01);
                    *reinterpret_cast<float2*>((float*)C + (size_t)(r0 + 8) * ldc + col) = make_float2(c10, c11);
                }
            }
        }
    }
}

// ---------------------------------------------------------------------------
// launch
// ---------------------------------------------------------------------------
extern "C" void kernel_launch(void* const* d_in, const int* in_sizes, int n_in,
                              void* d_out, int out_size)
{
    const float* x  = (const float*)d_in[0];
    const float* W1 = (const float*)d_in[1];
    const float* b1 = (const float*)d_in[2];
    const float* W2 = (const float*)d_in[3];
    const float* b2 = (const float*)d_in[4];
    float* out = (float*)d_out;

    __half *h_ptr, *A1, *B1, *A2, *B2;
    float *pix_ptr;
    cudaGetSymbolAddress((void**)&h_ptr,   g_h);
    cudaGetSymbolAddress((void**)&pix_ptr, g_pix);
    cudaGetSymbolAddress((void**)&A1, g_A1);
    cudaGetSymbolAddress((void**)&B1, g_B1);
    cudaGetSymbolAddress((void**)&A2, g_A2);
    cudaGetSymbolAddress((void**)&B2, g_B2);

    constexpr int SMEM1 = STAGES * (128 + 128) * 128;   // 98304, occ 2
    constexpr int SMEM2 = STAGES * (64 + 128) * 128;    // 73728, occ 3
    cudaFuncSetAttribute((const void*)gemm_fp16_mma<128, 128, 32, 64, 2, __half>,
                         cudaFuncAttributeMaxDynamicSharedMemorySize, SMEM1);
    cudaFuncSetAttribute((const void*)gemm_fp16_mma<64, 128, 32, 32, 3, float>,
                         cudaFuncAttributeMaxDynamicSharedMemorySize, SMEM2);

    { int n = M_TOK * DIM;   prep_x_kernel <<<(n + 255) / 256, 256>>>(x,  A1); }
    { int n = N1PAD * DIM;   prep_W1_kernel<<<(n + 255) / 256, 256>>>(W1, B1); }
    { int n = DIM * K2PAD;   prep_W2_kernel<<<(n + 255) / 256, 256>>>(W2, B2); }

    // GEMM1: g_h(fp16) = x @ W1^T + b1   (M=11520, N=1960(pad2048), K=512)
    {
        dim3 grid(N1PAD / 128, M_TOK / 128);   // (16, 90)
        gemm_fp16_mma<128, 128, 32, 64, 2, __half><<<grid, 256, SMEM1>>>(
            A1, B1, b1, h_ptr, DIM / 64, DIM * 2, HID, HID);
    }
    // fold + normalize + mask
    {
        int blocks = (NPIX + 255) / 256;
        fold_div_kernel<<<blocks, 256>>>(h_ptr, pix_ptr);
    }
    // unfold + GELU -> A2
    {
        long long n = (long long)M_TOK * K2PAD;
        prep_A2_kernel<<<(int)((n + 255) / 256), 256>>>(pix_ptr, A2);
    }
    // GEMM2: out = gelu(y) @ W2^T + b2   (M=11520, N=512, K=1960(pad1984))
    {
        dim3 grid(DIM / 128, M_TOK / 64);      // (4, 180)
        gemm_fp16_mma<64, 128, 32, 32, 3, float><<<grid, 256, SMEM2>>>(
            A2, B2, b2, out, K2PAD / 64, K2PAD * 2, DIM, DIM);
    }
}

// round 10
// speedup vs baseline: 1.3071x; 1.1174x over previous
#include <cuda_runtime.h>
#include <cuda_fp16.h>
#include <math.h>
#include <stdint.h>

// ---------------------------------------------------------------------------
// Problem constants
// ---------------------------------------------------------------------------
#define M_TOK   11520
#define DIM     512
#define HID     1960
#define BPRIME  16
#define NCH     40
#define OH      20
#define OW      36
#define LVEC    720
#define HP      66
#define WP      114
#define NPIX    (BPRIME*NCH*HP*WP)

#define N1PAD   2048
#define K2PAD   1984

// Scratch
__device__ __half g_h   [(size_t)M_TOK * HID];
__device__ __half g_pix [(size_t)NPIX];
__device__ __half g_A1  [(size_t)M_TOK * DIM];
__device__ __half g_B1  [(size_t)N1PAD * DIM];
__device__ __half g_A2  [(size_t)M_TOK * K2PAD];
__device__ __half g_B2  [(size_t)DIM   * K2PAD];
__device__ float  g_part[2][(size_t)M_TOK * DIM];   // split-K partials for GEMM2

__device__ __forceinline__ float gelu_exact(float v) {
    return 0.5f * v * (1.0f + erff(v * 0.70710678118654752f));
}

// ---------------------------------------------------------------------------
// operand prep kernels (vectorized x4)
// ---------------------------------------------------------------------------
__global__ void prep_x_kernel(const float4* __restrict__ x, __half2* __restrict__ A1)
{
    int idx = blockIdx.x * blockDim.x + threadIdx.x;
    if (idx >= M_TOK * DIM / 4) return;
    float4 v = x[idx];
    A1[idx * 2 + 0] = __floats2half2_rn(v.x, v.y);
    A1[idx * 2 + 1] = __floats2half2_rn(v.z, v.w);
}

__global__ void prep_W1_kernel(const float* __restrict__ W1, __half2* __restrict__ B1)
{
    int idx = blockIdx.x * blockDim.x + threadIdx.x;       // vec4 over N1PAD*DIM
    if (idx >= N1PAD * DIM / 4) return;
    int n = (idx * 4) / DIM;
    float4 v = make_float4(0.f, 0.f, 0.f, 0.f);
    if (n < HID) v = *reinterpret_cast<const float4*>(W1 + (size_t)idx * 4);
    B1[idx * 2 + 0] = __floats2half2_rn(v.x, v.y);
    B1[idx * 2 + 1] = __floats2half2_rn(v.z, v.w);
}

__global__ void prep_W2_kernel(const float* __restrict__ W2, __half2* __restrict__ B2)
{
    int idx = blockIdx.x * blockDim.x + threadIdx.x;       // vec4 over DIM*K2PAD
    if (idx >= DIM * K2PAD / 4) return;
    int n  = (idx * 4) / K2PAD;
    int j  = (idx * 4) - n * K2PAD;                        // 1960 % 4 == 0 -> all-or-none
    float4 v = make_float4(0.f, 0.f, 0.f, 0.f);
    if (j < HID) v = *reinterpret_cast<const float4*>(W2 + (size_t)n * HID + j);
    B2[idx * 2 + 0] = __floats2half2_rn(v.x, v.y);
    B2[idx * 2 + 1] = __floats2half2_rn(v.z, v.w);
}

// ---------------------------------------------------------------------------
// fold + normalize + border-mask (gather, no atomics), fp16 in/out
// ---------------------------------------------------------------------------
__global__ void fold_div_kernel(const __half* __restrict__ h, __half* __restrict__ pix)
{
    int idx = blockIdx.x * blockDim.x + threadIdx.x;
    if (idx >= NPIX) return;
    int ix = idx % WP;
    int t  = idx / WP;
    int iy = t % HP;  t /= HP;
    int c  = t % NCH;
    int b  = t / NCH;

    float val = 0.0f;
    if (iy >= 3 && iy < 63 && ix >= 3 && ix < 111) {
        int oy_lo = max(0, (iy - 4) / 3);
        int oy_hi = min(OH - 1, iy / 3);
        int ox_lo = max(0, (ix - 4) / 3);
        int ox_hi = min(OW - 1, ix / 3);
        int cnt = (oy_hi - oy_lo + 1) * (ox_hi - ox_lo + 1);
        float acc = 0.0f;
        for (int oy = oy_lo; oy <= oy_hi; oy++) {
            int kh = iy - 3 * oy;
            for (int ox = ox_lo; ox <= ox_hi; ox++) {
                int kw = ix - 3 * ox;
                int token = b * LVEC + oy * OW + ox;
                acc += __half2float(h[(size_t)token * HID + c * 49 + kh * 7 + kw]);
            }
        }
        val = acc / (float)cnt;
    }
    pix[idx] = __float2half(val);
}

// unfold + GELU -> fp16 A2 (2 elements / thread, half2 store)
__global__ void prep_A2_kernel(const __half* __restrict__ pix, __half2* __restrict__ A2)
{
    int idx = blockIdx.x * blockDim.x + threadIdx.x;
    if (idx >= M_TOK * (K2PAD / 2)) return;
    int token = idx / (K2PAD / 2);
    int j0    = (idx - token * (K2PAD / 2)) * 2;
    int b  = token / LVEC;
    int l  = token - b * LVEC;
    int oy = l / OW, ox = l - oy * OW;

    float g[2] = {0.0f, 0.0f};
#pragma unroll
    for (int e = 0; e < 2; e++) {
        int j = j0 + e;
        if (j < HID) {
            int c  = j / 49;
            int r  = j - c * 49;
            int kh = r / 7, kw = r - kh * 7;
            int iy = kh + 3 * oy;
            int ix = kw + 3 * ox;
            float y = __half2float(pix[(((size_t)b * NCH + c) * HP + iy) * WP + ix]);
            g[e] = gelu_exact(y);
        }
    }
    A2[idx] = __floats2half2_rn(g[0], g[1]);
}

// split-K combine: out = p0 + p1 + bias   (float4)
__global__ void combine_kernel(const float4* __restrict__ p0, const float4* __restrict__ p1,
                               const float4* __restrict__ bias, float4* __restrict__ out)
{
    int idx = blockIdx.x * blockDim.x + threadIdx.x;
    if (idx >= M_TOK * DIM / 4) return;
    float4 a = p0[idx], b = p1[idx];
    float4 bs = bias[idx & (DIM / 4 - 1)];
    out[idx] = make_float4(a.x + b.x + bs.x, a.y + b.y + bs.y,
                           a.z + b.z + bs.z, a.w + b.w + bs.w);
}

// ---------------------------------------------------------------------------
// fp16 mma.sync GEMM. C[m,n] = sum_k A[m,k]*B[n,k] (+ bias[n] if BIAS)
// 256 threads = 8 warps, BK=64 halves (SW128), 3-stage cp.async.
// blockIdx.z selects K range [0,KTsplit) or [KTsplit,KTtotal); C offset by
// z*part_stride.
// ---------------------------------------------------------------------------
#define STAGES 3

__device__ __forceinline__ uint32_t smem_u32(const void* p) {
    return (uint32_t)__cvta_generic_to_shared(p);
}

template<int BMt, int BNt, int WM, int WN, int MINCTA, bool BIAS, typename OutT>
__global__ __launch_bounds__(256, MINCTA)
void gemm_fp16_mma(const __half* __restrict__ A, const __half* __restrict__ B,
                   const float* __restrict__ bias, OutT* __restrict__ C,
                   int KTsplit, int KTtotal, int kbytes, int Nstore, int ldc,
                   size_t part_stride)
{
    constexpr int STAGE_BYTES = (BMt + BNt) * 128;
    constexpr int A_BYTES     = BMt * 128;
    constexpr int NWN  = BNt / WN;
    constexpr int NI   = WM / 16;
    constexpr int NB16 = WN / 16;
    constexpr int NJ   = WN / 8;
    static_assert((BMt / WM) * NWN == 8, "8 warps");

    extern __shared__ char smem[];
    uint32_t sbase = smem_u32(smem);
    const int tid  = threadIdx.x;
    const int wid  = tid >> 5;
    const int lane = tid & 31;
    const int wm   = wid / NWN;
    const int wn   = wid % NWN;
    const int m0   = blockIdx.y * BMt;
    const int n0   = blockIdx.x * BNt;
    const int z    = blockIdx.z;
    const int kt_lo = z ? KTsplit : 0;
    const int kt_hi = z ? KTtotal : KTsplit;
    C += (size_t)z * part_stride;

    const char* Ab = (const char*)A + (size_t)m0 * kbytes;
    const char* Bb = (const char*)B + (size_t)n0 * kbytes;

    float acc[NI][NJ][4];
#pragma unroll
    for (int i = 0; i < NI; i++)
#pragma unroll
        for (int j = 0; j < NJ; j++)
#pragma unroll
            for (int q = 0; q < 4; q++) acc[i][j][q] = 0.0f;

    auto load_stage = [&](int s, int kt2) {
        uint32_t st = sbase + s * STAGE_BYTES;
        size_t koff = (size_t)kt2 * 128;
#pragma unroll
        for (int i = 0; i < BMt / 32; i++) {
            int id  = tid + i * 256;
            int row = id >> 3;
            int c   = id & 7;
            uint32_t so = (uint32_t)(row * 128 + ((c ^ (row & 7)) << 4));
            const char* ga = Ab + (size_t)row * kbytes + koff + ((size_t)c << 4);
            asm volatile("cp.async.cg.shared.global [%0], [%1], 16;" :: "r"(st + so), "l"(ga) : "memory");
        }
#pragma unroll
        for (int i = 0; i < BNt / 32; i++) {
            int id  = tid + i * 256;
            int row = id >> 3;
            int c   = id & 7;
            uint32_t so = (uint32_t)(row * 128 + ((c ^ (row & 7)) << 4));
            const char* gb = Bb + (size_t)row * kbytes + koff + ((size_t)c << 4);
            asm volatile("cp.async.cg.shared.global [%0], [%1], 16;" :: "r"(st + A_BYTES + so), "l"(gb) : "memory");
        }
        asm volatile("cp.async.commit_group;" ::: "memory");
    };

    const int lrow = lane & 15;
    const int lch  = lane >> 4;
    uint32_t offA[NI], offB[NB16];
#pragma unroll
    for (int i = 0; i < NI; i++) {
        int r = wm * WM + i * 16 + lrow;
        offA[i] = (uint32_t)(r * 128 + ((lch ^ (r & 7)) << 4));
    }
#pragma unroll
    for (int j = 0; j < NB16; j++) {
        int r = wn * WN + j * 16 + lrow;
        offB[j] = (uint32_t)(A_BYTES + r * 128 + ((lch ^ (r & 7)) << 4));
    }

    // prologue
#pragma unroll
    for (int p = 0; p < STAGES - 1; p++) load_stage(p, kt_lo + p);

    for (int kt = kt_lo; kt < kt_hi; kt++) {
        int s = (kt - kt_lo) % STAGES;
        asm volatile("cp.async.wait_group 1;" ::: "memory");
        __syncthreads();

        int ktn = kt + STAGES - 1;
        if (ktn < kt_hi) load_stage((ktn - kt_lo) % STAGES, ktn);
        else             asm volatile("cp.async.commit_group;" ::: "memory");

        uint32_t sA = sbase + s * STAGE_BYTES;

#pragma unroll
        for (int k16 = 0; k16 < 4; k16++) {
            const uint32_t kx = (uint32_t)(k16 << 5);
            uint32_t a[NI][4], b[NB16][4];
#pragma unroll
            for (int i = 0; i < NI; i++) {
                asm volatile("ldmatrix.sync.aligned.m8n8.x4.shared.b16 {%0,%1,%2,%3}, [%4];"
                             : "=r"(a[i][0]), "=r"(a[i][1]), "=r"(a[i][2]), "=r"(a[i][3])
                             : "r"(sA + (offA[i] ^ kx)));
            }
#pragma unroll
            for (int j = 0; j < NB16; j++) {
                asm volatile("ldmatrix.sync.aligned.m8n8.x4.shared.b16 {%0,%1,%2,%3}, [%4];"
                             : "=r"(b[j][0]), "=r"(b[j][1]), "=r"(b[j][2]), "=r"(b[j][3])
                             : "r"(sA + (offB[j] ^ kx)));
            }
#pragma unroll
            for (int i = 0; i < NI; i++) {
#pragma unroll
                for (int jn = 0; jn < NJ; jn++) {
                    int jj = jn >> 1;
                    uint32_t b0 = (jn & 1) ? b[jj][1] : b[jj][0];
                    uint32_t b1 = (jn & 1) ? b[jj][3] : b[jj][2];
                    asm volatile(
                        "mma.sync.aligned.m16n8k16.row.col.f32.f16.f16.f32 "
                        "{%0,%1,%2,%3}, {%4,%5,%6,%7}, {%8,%9}, {%0,%1,%2,%3};"
                        : "+f"(acc[i][jn][0]), "+f"(acc[i][jn][1]),
                          "+f"(acc[i][jn][2]), "+f"(acc[i][jn][3])
                        : "r"(a[i][0]), "r"(a[i][1]), "r"(a[i][2]), "r"(a[i][3]),
                          "r"(b0), "r"(b1));
                }
            }
        }
    }

    // epilogue
    const int g  = lane >> 2;
    const int tg = lane & 3;
#pragma unroll
    for (int i = 0; i < NI; i++) {
        int r0 = m0 + wm * WM + i * 16 + g;
#pragma unroll
        for (int jn = 0; jn < NJ; jn++) {
            int col = n0 + wn * WN + jn * 8 + tg * 2;
            if (col < Nstore) {
                float bx = BIAS ? bias[col]     : 0.0f;
                float by = BIAS ? bias[col + 1] : 0.0f;
                float c00 = acc[i][jn][0] + bx, c01 = acc[i][jn][1] + by;
                float c10 = acc[i][jn][2] + bx, c11 = acc[i][jn][3] + by;
                if constexpr (sizeof(OutT) == 2) {
                    *reinterpret_cast<__half2*>((__half*)C + (size_t)r0       * ldc + col) = __floats2half2_rn(c00, c01);
                    *reinterpret_cast<__half2*>((__half*)C + (size_t)(r0 + 8) * ldc + col) = __floats2half2_rn(c10, c11);
                } else {
                    *reinterpret_cast<float2*>((float*)C + (size_t)r0       * ldc + col) = make_float2(c00, c01);
                    *reinterpret_cast<float2*>((float*)C + (size_t)(r0 + 8) * ldc + col) = make_float2(c10, c11);
                }
            }
        }
    }
}

// ---------------------------------------------------------------------------
// launch
// ---------------------------------------------------------------------------
extern "C" void kernel_launch(void* const* d_in, const int* in_sizes, int n_in,
                              void* d_out, int out_size)
{
    const float* x  = (const float*)d_in[0];
    const float* W1 = (const float*)d_in[1];
    const float* b1 = (const float*)d_in[2];
    const float* W2 = (const float*)d_in[3];
    const float* b2 = (const float*)d_in[4];
    float* out = (float*)d_out;

    __half *h_ptr, *pix_ptr, *A1, *B1, *A2, *B2;
    float *part_ptr;
    cudaGetSymbolAddress((void**)&h_ptr,   g_h);
    cudaGetSymbolAddress((void**)&pix_ptr, g_pix);
    cudaGetSymbolAddress((void**)&A1, g_A1);
    cudaGetSymbolAddress((void**)&B1, g_B1);
    cudaGetSymbolAddress((void**)&A2, g_A2);
    cudaGetSymbolAddress((void**)&B2, g_B2);
    cudaGetSymbolAddress((void**)&part_ptr, g_part);

    constexpr int SMEM12 = STAGES * (128 + 128) * 128;   // 98304, occ 2
    cudaFuncSetAttribute((const void*)gemm_fp16_mma<128, 128, 32, 64, 2, true, __half>,
                         cudaFuncAttributeMaxDynamicSharedMemorySize, SMEM12);
    cudaFuncSetAttribute((const void*)gemm_fp16_mma<128, 128, 32, 64, 2, false, float>,
                         cudaFuncAttributeMaxDynamicSharedMemorySize, SMEM12);

    { int n = M_TOK * DIM / 4;   prep_x_kernel <<<(n + 255) / 256, 256>>>((const float4*)x, (__half2*)A1); }
    { int n = N1PAD * DIM / 4;   prep_W1_kernel<<<(n + 255) / 256, 256>>>(W1, (__half2*)B1); }
    { int n = DIM * K2PAD / 4;   prep_W2_kernel<<<(n + 255) / 256, 256>>>(W2, (__half2*)B2); }

    // GEMM1: g_h(fp16) = x @ W1^T + b1   (M=11520, N=1960(pad2048), K=512)
    {
        dim3 grid(N1PAD / 128, M_TOK / 128, 1);   // (16, 90)
        gemm_fp16_mma<128, 128, 32, 64, 2, true, __half><<<grid, 256, SMEM12>>>(
            A1, B1, b1, h_ptr, DIM / 64, DIM / 64, DIM * 2, HID, HID, 0);
    }
    // fold + normalize + mask (fp16 pix)
    {
        int blocks = (NPIX + 255) / 256;
        fold_div_kernel<<<blocks, 256>>>(h_ptr, pix_ptr);
    }
    // unfold + GELU -> A2 (half2)
    {
        int n = M_TOK * (K2PAD / 2);
        prep_A2_kernel<<<(n + 255) / 256, 256>>>(pix_ptr, (__half2*)A2);
    }
    // GEMM2 split-K: partials  (M=11520, N=512, K split 960 + 1024)
    {
        dim3 grid(DIM / 128, M_TOK / 128, 2);     // (4, 90, 2) = 720 CTAs
        gemm_fp16_mma<128, 128, 32, 64, 2, false, float><<<grid, 256, SMEM12>>>(
            A2, B2, nullptr, part_ptr, 960 / 64, K2PAD / 64, K2PAD * 2, DIM, DIM,
            (size_t)M_TOK * DIM);
    }
    // combine: out = p0 + p1 + b2
    {
        int n = M_TOK * DIM / 4;
        combine_kernel<<<(n + 255) / 256, 256>>>(
            (const float4*)part_ptr, (const float4*)(part_ptr + (size_t)M_TOK * DIM),
            (const float4*)b2, (float4*)out);
    }
}